// round 10
// baseline (speedup 1.0000x reference)
#include <cuda_runtime.h>
#include <cstdint>

// ASG loss = FCC (log-partition over all paths) - FAC (forced alignment).
// T=512, B=32, V=512, L=128 (fixed by dataset).
//
// FCC: unnormalized probability recursion v' = exp(lp) * (E v), E in regs.
// Cluster of 8 CTAs per 2 batches, 1024 threads/CTA (32 warps, 8/SMSP) so
// the per-step latency chain (wake, LDS, shuffle tree, st.async issue) is
// hidden by co-resident warps. Each warp: 2 rows x 2 batches, lanes split
// j 32-way (16 j each), 6-shuffle merge tree; results land on lanes
// {0,8,16,24} which push scalar 4B SELF-SIGNALING st.async messages to all
// 8 ranks (protocol identical to the 825us best: 2 tx-barriers,
// expect_tx=4096B, parity ((t-1)>>1)&1, re-arm after consume).
// FAC: separate CTAs, 1 warp/batch, register-resident.

namespace {
constexpr int T_ = 512, B_ = 32, V_ = 512, L_ = 128;
constexpr int CSZ = 8;      // cluster size
constexpr int ISL = 64;     // i-rows per CTA
constexpr int NTHR = 1024;
constexpr int NFCC = 16;    // FCC clusters (2 batches each)
constexpr float NEG = -1000000000.0f;
constexpr unsigned FILL_BYTES = 2u * V_ * 4u;   // 4096 B per fill
}

__device__ float g_fcc[B_];
__device__ float g_fac[B_];
__device__ unsigned g_done[B_];   // parity counter, never reset

static __device__ __forceinline__ unsigned cta_rank() {
    unsigned r; asm("mov.u32 %0, %%cluster_ctarank;" : "=r"(r)); return r;
}
static __device__ __forceinline__ unsigned su32(const void* p) {
    unsigned a;
    asm("{ .reg .u64 t; cvta.to.shared.u64 t, %1; cvt.u32.u64 %0, t; }"
        : "=r"(a) : "l"(p));
    return a;
}
static __device__ __forceinline__ unsigned mapa_r(unsigned a, unsigned r) {
    unsigned o;
    asm("mapa.shared::cluster.u32 %0, %1, %2;" : "=r"(o) : "r"(a), "r"(r));
    return o;
}
static __device__ __forceinline__ void csync() {
    asm volatile("barrier.cluster.arrive.aligned;" ::: "memory");
    asm volatile("barrier.cluster.wait.aligned;" ::: "memory");
}
static __device__ __forceinline__ void mbar_init(unsigned a, unsigned cnt) {
    asm volatile("mbarrier.init.shared.b64 [%0], %1;" :: "r"(a), "r"(cnt) : "memory");
}
static __device__ __forceinline__ void mbar_expect(unsigned a, unsigned tx) {
    asm volatile("mbarrier.arrive.expect_tx.shared.b64 _, [%0], %1;"
                 :: "r"(a), "r"(tx) : "memory");
}
// Self-signaling remote store: data lands in peer SMEM, credits 4 bytes on
// the peer's mbarrier when complete.
static __device__ __forceinline__ void st_async32(unsigned a, float v, unsigned mb) {
    asm volatile("st.async.shared::cluster.mbarrier::complete_tx::bytes.b32 [%0], %1, [%2];"
                 :: "r"(a), "r"(__float_as_uint(v)), "r"(mb) : "memory");
}
static __device__ __forceinline__ void mbar_wait(unsigned a, unsigned parity) {
    unsigned done;
    asm volatile(
        "{\n\t.reg .pred p;\n\t"
        "mbarrier.try_wait.parity.acquire.cluster.shared::cta.b64 p, [%1], %2;\n\t"
        "selp.b32 %0, 1, 0, p;\n\t}"
        : "=r"(done) : "r"(a), "r"(parity) : "memory");
    if (!done) {
        asm volatile(
            "{\n\t.reg .pred P1;\n\t"
            "WL_%=:\n\t"
            "mbarrier.try_wait.parity.acquire.cluster.shared::cta.b64 P1, [%0], %1, 0x989680;\n\t"
            "@P1 bra.uni WD_%=;\n\t"
            "bra.uni WL_%=;\n\t"
            "WD_%=:\n\t}"
            :: "r"(a), "r"(parity) : "memory");
    }
}
static __device__ __forceinline__ unsigned long long fma2(
    unsigned long long a, unsigned long long b, unsigned long long c) {
    unsigned long long d;
    asm("fma.rn.f32x2 %0, %1, %2, %3;" : "=l"(d) : "l"(a), "l"(b), "l"(c));
    return d;
}
static __device__ __forceinline__ unsigned long long packf2(float lo, float hi) {
    unsigned long long d;
    asm("mov.b64 %0, {%1,%2};" : "=l"(d) : "f"(lo), "f"(hi));
    return d;
}
static __device__ __forceinline__ float pairsum(unsigned long long a) {
    float lo, hi;
    asm("mov.b64 {%0,%1}, %2;" : "=f"(lo), "=f"(hi) : "l"(a));
    return lo + hi;
}
// Merge-reduce step: lanes with (lane & m)==0 end carrying a's pair-sum,
// lanes with (lane & m)!=0 end carrying b's.
static __device__ __forceinline__ float mrg(float a, float b, int m, int lane) {
    float send = (lane & m) ? a : b;
    float keep = (lane & m) ? b : a;
    return keep + __shfl_xor_sync(~0u, send, m);
}

// Second arriver (parity odd) of {fcc, fac} writes the output.
static __device__ __forceinline__ void publish(int b, float val, bool is_fcc,
                                               float* __restrict__ out) {
    if (is_fcc) g_fcc[b] = val; else g_fac[b] = val;
    __threadfence();
    unsigned old = atomicAdd(&g_done[b], 1u);
    if (old & 1u) {
        __threadfence();
        out[b] = g_fcc[b] - g_fac[b];
    }
}

__global__ void __launch_bounds__(NTHR, 1) __cluster_dims__(CSZ, 1, 1)
asg_main(const float* __restrict__ lp, const float* __restrict__ tr,
         const int* __restrict__ tgt, const int* __restrict__ ilen,
         const int* __restrict__ tlen, float* __restrict__ out)
{
    __shared__ __align__(16) float s_u[2][2][V_];        // double-buffered v
    __shared__ __align__(8) unsigned long long s_mbar[2];

    const int tid  = threadIdx.x;
    const int lane = tid & 31;
    const int wid  = tid >> 5;
    const int cid  = (int)blockIdx.x >> 3;

    if (cid < NFCC) {
        // =============================== FCC ===============================
        const unsigned r = cta_rank();
        const int b0 = 2 * cid, b1 = 2 * cid + 1;
        const int len0 = ilen[b0], len1 = ilen[b1];

        // Value/push lanes {0,8,16,24}: lane ends with the full sum for
        // row 2*wid + (lane>>4), batch (lane>>3)&1.
        const bool isp = (lane & 7) == 0;
        const int pbb  = (lane >> 3) & 1;
        const int prow = (int)r * ISL + 2 * wid + (lane >> 4);   // global row

        const unsigned ubase  = su32(&s_u[0][0][0]);
        const unsigned mloc0  = su32(&s_mbar[0]);
        const unsigned mdelta = mloc0 - ubase;

        if (tid == 0) {
            mbar_init(mloc0, 1);
            mbar_init(mloc0 + 8, 1);
            mbar_expect(mloc0 + 8, FILL_BYTES);   // fill@t=0 targets mbar[1]
        }

        // E registers: warp w owns rows r*64 + 2w + rr (rr<2); lane owns
        // j in {4*lane + 128k}: conflict-free interleaved map. 16 u64 regs.
        unsigned long long e2[16];
        #pragma unroll
        for (int rr = 0; rr < 2; ++rr) {
            const int row = (int)r * ISL + 2 * wid + rr;
            #pragma unroll
            for (int k = 0; k < 4; ++k) {
                float4 v4 = *(const float4*)(tr + (size_t)row * V_ + 4 * lane + 128 * k);
                e2[rr * 8 + 2 * k]     = packf2(__expf(v4.x), __expf(v4.y));
                e2[rr * 8 + 2 * k + 1] = packf2(__expf(v4.z), __expf(v4.w));
            }
        }

        // v_0 = exp(lp[0,b,:]); every CTA initializes buffer 0 locally.
        if (tid < V_)       s_u[0][0][tid]       = __expf(lp[(size_t)b0 * V_ + tid]);
        else                s_u[0][1][tid - V_]  = __expf(lp[(size_t)b1 * V_ + (tid - V_)]);
        __syncthreads();
        csync();   // peers' mbar init + expect + buffers visible

        for (int t = 0; t < T_; ++t) {
            const int buf = t & 1;

            // Prefetch exp(lp[t+1]) for this push lane's (row,batch)
            float el = 0.f;
            if (isp && t + 1 < T_)
                el = __expf(lp[((size_t)(t + 1) * B_ + (pbb ? b1 : b0)) * V_ + prow]);

            if (t) mbar_wait(mloc0 + (unsigned)buf * 8, (unsigned)(((t - 1) >> 1) & 1));

            // Arm this mbar for its next fill (fill@t+1), after its consume
            if (tid == 0 && t + 3 <= T_)
                mbar_expect(mloc0 + (unsigned)buf * 8, FILL_BYTES);

            // Score capture (once per batch): lse(alpha_t) = log sum_j v_j
            if (r == 0 && (wid == 8 || wid == 9)) {
                const int bs = wid - 8;
                if (t == (bs ? len1 : len0) - 1) {
                    float s = 0.f;
                    #pragma unroll
                    for (int k = 0; k < 16; ++k) s += s_u[buf][bs][lane + 32 * k];
                    #pragma unroll
                    for (int mk = 16; mk; mk >>= 1) s += __shfl_xor_sync(~0u, s, mk);
                    if (lane == 0) publish(bs ? b1 : b0, logf(s), true, out);
                }
            }
            if (t == T_ - 1) break;

            // Phase A: dots for 2 rows x 2 batches, lanes split j 32-way
            unsigned long long a00 = 0ull, a01 = 0ull, a10 = 0ull, a11 = 0ull;
            #pragma unroll
            for (int k = 0; k < 4; ++k) {
                ulonglong2 q0 = *(const ulonglong2*)&s_u[buf][0][4 * lane + 128 * k];
                ulonglong2 q1 = *(const ulonglong2*)&s_u[buf][1][4 * lane + 128 * k];
                a00 = fma2(e2[2 * k],         q0.x, a00);
                a00 = fma2(e2[2 * k + 1],     q0.y, a00);
                a01 = fma2(e2[2 * k],         q1.x, a01);
                a01 = fma2(e2[2 * k + 1],     q1.y, a01);
                a10 = fma2(e2[8 + 2 * k],     q0.x, a10);
                a10 = fma2(e2[8 + 2 * k + 1], q0.y, a10);
                a11 = fma2(e2[8 + 2 * k],     q1.x, a11);
                a11 = fma2(e2[8 + 2 * k + 1], q1.y, a11);
            }

            // 6-shuffle merge: lane0 -> (rr0,b0), lane8 -> (rr0,b1),
            // lane16 -> (rr1,b0), lane24 -> (rr1,b1).
            float f0 = pairsum(a00), f1 = pairsum(a01);
            float f2 = pairsum(a10), f3 = pairsum(a11);
            float g0 = mrg(f0, f2, 16, lane);   // bit16 selects rr
            float g1 = mrg(f1, f3, 16, lane);
            float h  = mrg(g0, g1, 8, lane);    // bit8 selects batch
            h += __shfl_xor_sync(~0u, h, 4);
            h += __shfl_xor_sync(~0u, h, 2);
            h += __shfl_xor_sync(~0u, h, 1);

            // Push v' = el * h to all 8 ranks (scalar 4B self-signaling).
            if (isp) {
                const float v = el * h;
                const int nbuf = buf ^ 1;
                const unsigned off = ((unsigned)(nbuf * 2 + pbb) * V_ + (unsigned)prow) * 4u;
                const unsigned mboff = mdelta + (unsigned)nbuf * 8u;
                #pragma unroll
                for (int rk = 0; rk < CSZ; ++rk) {
                    const unsigned base = mapa_r(ubase, (unsigned)rk);
                    st_async32(base + off, v, base + mboff);
                }
            }
        }
        csync();   // no CTA exits while peers may still write its SMEM
    } else {
        // =============================== FAC ===============================
        if (wid >= 4) return;
        const int b = ((int)blockIdx.x - NFCC * CSZ) * 4 + wid;   // 0..31
        const int il = ilen[b], tl = tlen[b];

        int tg[4];
        #pragma unroll
        for (int k = 0; k < 4; ++k) tg[k] = tgt[b * L_ + lane * 4 + k];

        float ts[4], tp[4];
        #pragma unroll
        for (int k = 0; k < 4; ++k) ts[k] = tr[tg[k] * V_ + tg[k]];
        const int tprev = __shfl_up_sync(~0u, tg[3], 1);
        tp[0] = tr[tg[0] * V_ + tprev];           // garbage on lane 0, never used
        tp[1] = tr[tg[1] * V_ + tg[0]];
        tp[2] = tr[tg[2] * V_ + tg[1]];
        tp[3] = tr[tg[3] * V_ + tg[2]];

        float beta[4];
        #pragma unroll
        for (int k = 0; k < 4; ++k)
            beta[k] = (lane == 0 && k == 0) ? lp[(size_t)b * V_ + tg[0]] : NEG;

        float emn[4];
        #pragma unroll
        for (int k = 0; k < 4; ++k)
            emn[k] = lp[((size_t)1 * B_ + b) * V_ + tg[k]];

        for (int t = 0; t < T_; ++t) {
            if (t == il - 1) {
                const int lsel = tl - 1;
                if (lane == (lsel >> 2)) publish(b, beta[lsel & 3], false, out);
            }
            if (t == T_ - 1) break;

            float em[4];
            #pragma unroll
            for (int k = 0; k < 4; ++k) em[k] = emn[k];
            if (t + 2 < T_) {
                #pragma unroll
                for (int k = 0; k < 4; ++k)
                    emn[k] = lp[((size_t)(t + 2) * B_ + b) * V_ + tg[k]];
            }

            const float bprev = __shfl_up_sync(~0u, beta[3], 1);
            float prevs[4] = {bprev, beta[0], beta[1], beta[2]};
            #pragma unroll
            for (int k = 0; k < 4; ++k) {
                float stay = beta[k] + ts[k];
                float move = (lane == 0 && k == 0) ? NEG : prevs[k] + tp[k];
                float hi = fmaxf(stay, move);
                float lo = fminf(stay, move);
                beta[k] = em[k] + hi + __logf(1.f + __expf(lo - hi));
            }
        }
    }
}

extern "C" void kernel_launch(void* const* d_in, const int* in_sizes, int n_in,
                              void* d_out, int out_size) {
    const float* lp  = (const float*)d_in[0];
    const float* tr  = (const float*)d_in[1];
    const int*   tgt = (const int*)d_in[2];
    const int*   il  = (const int*)d_in[3];
    const int*   tl  = (const int*)d_in[4];
    (void)in_sizes; (void)n_in; (void)out_size;

    asg_main<<<NFCC * CSZ + CSZ, NTHR>>>(lp, tr, tgt, il, tl, (float*)d_out);
}

// round 11
// speedup vs baseline: 1.4239x; 1.4239x over previous
#include <cuda_runtime.h>
#include <cuda_bf16.h>
#include <cstdint>

// ASG loss = FCC (log-partition over all paths) - FAC (forced alignment).
// T=512, B=32, V=512, L=128 (fixed by dataset).
//
// FCC: unnormalized probability recursion v' = exp(lp) * (E v), E fp32 in
// regs. Cluster of 8 CTAs per 2 batches. Per-step exchange = SELF-SIGNALING
// st.async stores (protocol identical to the 825us best), but v travels as
// BF16: fills are 2048B instead of 4096B (tests the receiver-bandwidth
// hypothesis). Phase A loads bf16x2 words and expands to packed f32x2 with
// 2 ALU ops (<<16 / &0xffff0000); FMA math unchanged. Push side pairs rows
// (rr,rr+1) with one shfl and sends one cvt.rn.bf16x2 word per rank from
// lanes {0,4,16,20}.
// FAC: separate CTAs, 1 warp/batch, register-resident, fp32 throughout.

namespace {
constexpr int T_ = 512, B_ = 32, V_ = 512, L_ = 128;
constexpr int CSZ = 8;      // cluster size
constexpr int ISL = 64;     // i-rows per CTA
constexpr int NTHR = 512;
constexpr int NFCC = 16;    // FCC clusters (2 batches each)
constexpr float NEG = -1000000000.0f;
constexpr unsigned FILL_BYTES = 2u * V_ * 2u;   // 2048 B per fill (bf16)
}

__device__ float g_fcc[B_];
__device__ float g_fac[B_];
__device__ unsigned g_done[B_];   // parity counter, never reset

static __device__ __forceinline__ unsigned cta_rank() {
    unsigned r; asm("mov.u32 %0, %%cluster_ctarank;" : "=r"(r)); return r;
}
static __device__ __forceinline__ unsigned su32(const void* p) {
    unsigned a;
    asm("{ .reg .u64 t; cvta.to.shared.u64 t, %1; cvt.u32.u64 %0, t; }"
        : "=r"(a) : "l"(p));
    return a;
}
static __device__ __forceinline__ unsigned mapa_r(unsigned a, unsigned r) {
    unsigned o;
    asm("mapa.shared::cluster.u32 %0, %1, %2;" : "=r"(o) : "r"(a), "r"(r));
    return o;
}
static __device__ __forceinline__ void csync() {
    asm volatile("barrier.cluster.arrive.aligned;" ::: "memory");
    asm volatile("barrier.cluster.wait.aligned;" ::: "memory");
}
static __device__ __forceinline__ void mbar_init(unsigned a, unsigned cnt) {
    asm volatile("mbarrier.init.shared.b64 [%0], %1;" :: "r"(a), "r"(cnt) : "memory");
}
static __device__ __forceinline__ void mbar_expect(unsigned a, unsigned tx) {
    asm volatile("mbarrier.arrive.expect_tx.shared.b64 _, [%0], %1;"
                 :: "r"(a), "r"(tx) : "memory");
}
// Self-signaling remote store: 4B payload (one bf16x2 word), credits 4
// bytes on the destination's mbarrier when complete.
static __device__ __forceinline__ void st_async32u(unsigned a, unsigned v, unsigned mb) {
    asm volatile("st.async.shared::cluster.mbarrier::complete_tx::bytes.b32 [%0], %1, [%2];"
                 :: "r"(a), "r"(v), "r"(mb) : "memory");
}
static __device__ __forceinline__ void mbar_wait(unsigned a, unsigned parity) {
    unsigned done;
    asm volatile(
        "{\n\t.reg .pred p;\n\t"
        "mbarrier.try_wait.parity.acquire.cluster.shared::cta.b64 p, [%1], %2;\n\t"
        "selp.b32 %0, 1, 0, p;\n\t}"
        : "=r"(done) : "r"(a), "r"(parity) : "memory");
    if (!done) {
        asm volatile(
            "{\n\t.reg .pred P1;\n\t"
            "WL_%=:\n\t"
            "mbarrier.try_wait.parity.acquire.cluster.shared::cta.b64 P1, [%0], %1, 0x989680;\n\t"
            "@P1 bra.uni WD_%=;\n\t"
            "bra.uni WL_%=;\n\t"
            "WD_%=:\n\t}"
            :: "r"(a), "r"(parity) : "memory");
    }
}
static __device__ __forceinline__ unsigned long long fma2(
    unsigned long long a, unsigned long long b, unsigned long long c) {
    unsigned long long d;
    asm("fma.rn.f32x2 %0, %1, %2, %3;" : "=l"(d) : "l"(a), "l"(b), "l"(c));
    return d;
}
static __device__ __forceinline__ unsigned long long packf2(float lo, float hi) {
    unsigned long long d;
    asm("mov.b64 %0, {%1,%2};" : "=l"(d) : "f"(lo), "f"(hi));
    return d;
}
static __device__ __forceinline__ unsigned long long packu2(unsigned lo, unsigned hi) {
    unsigned long long d;
    asm("mov.b64 %0, {%1,%2};" : "=l"(d) : "r"(lo), "r"(hi));
    return d;
}
// Expand one bf16x2 word {hi=j1, lo=j0} to a packed f32x2 {lo=f32(j0), hi=f32(j1)}.
static __device__ __forceinline__ unsigned long long bf2f2(unsigned w) {
    return packu2(w << 16, w & 0xffff0000u);
}
static __device__ __forceinline__ float pairsum(unsigned long long a) {
    float lo, hi;
    asm("mov.b64 {%0,%1}, %2;" : "=f"(lo), "=f"(hi) : "l"(a));
    return lo + hi;
}
// Merge-reduce step: combine two per-lane partial values; lanes with
// (lane & m) carry the 'b' index forward.
static __device__ __forceinline__ float mrg(float a, float b, int m, int lane) {
    float send = (lane & m) ? a : b;
    float keep = (lane & m) ? b : a;
    return keep + __shfl_xor_sync(~0u, send, m);
}

// Second arriver (parity odd) of {fcc, fac} writes the output.
static __device__ __forceinline__ void publish(int b, float val, bool is_fcc,
                                               float* __restrict__ out) {
    if (is_fcc) g_fcc[b] = val; else g_fac[b] = val;
    __threadfence();
    unsigned old = atomicAdd(&g_done[b], 1u);
    if (old & 1u) {
        __threadfence();
        out[b] = g_fcc[b] - g_fac[b];
    }
}

__global__ void __launch_bounds__(NTHR, 1) __cluster_dims__(CSZ, 1, 1)
asg_main(const float* __restrict__ lp, const float* __restrict__ tr,
         const int* __restrict__ tgt, const int* __restrict__ ilen,
         const int* __restrict__ tlen, float* __restrict__ out)
{
    __shared__ __align__(16) __nv_bfloat16 s_u[2][2][V_];   // double-buffered v (bf16)
    __shared__ __align__(8) unsigned long long s_mbar[2];

    const int tid  = threadIdx.x;
    const int lane = tid & 31;
    const int wid  = tid >> 5;
    const int cid  = (int)blockIdx.x >> 3;

    if (cid < NFCC) {
        // =============================== FCC ===============================
        const unsigned r = cta_rank();
        const int b0 = 2 * cid, b1 = 2 * cid + 1;
        const int len0 = ilen[b0], len1 = ilen[b1];

        // Value lanes (lane&3)==0 hold the 8 final sums; idx = lane>>2 =
        // rr*2 + bb. Push lanes {0,4,16,20} (idx even in rr: rr in {0,2})
        // push the bf16x2 pair (row rr, row rr+1) of batch bb.
        const bool isv = (lane & 3) == 0;
        const int pbb  = (lane >> 2) & 1;
        const int prr  = lane >> 3;                       // 0..3 on value lanes
        const int prow = (int)r * ISL + wid * 4 + prr;    // global row
        const bool isp = (lane & 11) == 0;                // lanes 0,4,16,20

        const unsigned ubase  = su32(&s_u[0][0][0]);
        const unsigned mloc0  = su32(&s_mbar[0]);
        const unsigned mdelta = mloc0 - ubase;
        unsigned pb[CSZ];
        #pragma unroll
        for (int rk = 0; rk < CSZ; ++rk) pb[rk] = mapa_r(ubase, (unsigned)rk);

        if (tid == 0) {
            mbar_init(mloc0, 1);
            mbar_init(mloc0 + 8, 1);
            mbar_expect(mloc0 + 8, FILL_BYTES);   // fill@t=0 targets mbar[1]
        }

        // E registers: warp w owns rows r*64 + 4w + rr (rr<4); lane owns
        // j in {4*lane + 128k + m}: conflict-free interleaved map.
        unsigned long long e2[32];
        #pragma unroll
        for (int rr = 0; rr < 4; ++rr) {
            const int row = (int)r * ISL + wid * 4 + rr;
            #pragma unroll
            for (int k = 0; k < 4; ++k) {
                float4 v4 = *(const float4*)(tr + (size_t)row * V_ + 4 * lane + 128 * k);
                e2[rr * 8 + 2 * k]     = packf2(__expf(v4.x), __expf(v4.y));
                e2[rr * 8 + 2 * k + 1] = packf2(__expf(v4.z), __expf(v4.w));
            }
        }

        // v_0 = exp(lp[0,b,:]) quantized to bf16; full local init.
        s_u[0][0][tid] = __float2bfloat16(__expf(lp[(size_t)b0 * V_ + tid]));
        s_u[0][1][tid] = __float2bfloat16(__expf(lp[(size_t)b1 * V_ + tid]));
        __syncthreads();
        csync();   // peers' mbar init + expect + buffers visible

        for (int t = 0; t < T_; ++t) {
            const int buf = t & 1;

            // Prefetch exp(lp[t+1]) for this lane's (row,batch), before wait
            float el = 0.f;
            if (isv && t + 1 < T_)
                el = __expf(lp[((size_t)(t + 1) * B_ + (pbb ? b1 : b0)) * V_ + prow]);

            if (t) mbar_wait(mloc0 + (unsigned)buf * 8, (unsigned)(((t - 1) >> 1) & 1));

            // Arm this mbar for its next fill (fill@t+1), after its consume
            if (tid == 0 && t + 3 <= T_)
                mbar_expect(mloc0 + (unsigned)buf * 8, FILL_BYTES);

            // Score capture (once per batch): lse(alpha_t) = log sum_j v_j
            if (r == 0 && (wid == 8 || wid == 9)) {
                const int bs = wid - 8;
                if (t == (bs ? len1 : len0) - 1) {
                    float s = 0.f;
                    #pragma unroll
                    for (int k = 0; k < 16; ++k)
                        s += __bfloat162float(s_u[buf][bs][lane + 32 * k]);
                    #pragma unroll
                    for (int mk = 16; mk; mk >>= 1) s += __shfl_xor_sync(~0u, s, mk);
                    if (lane == 0) publish(bs ? b1 : b0, logf(s), true, out);
                }
            }
            if (t == T_ - 1) break;

            // Phase A: complete dots for 4 rows x 2 batches, lanes split j
            // 32-way. Loads are bf16x2 words, expanded to packed f32x2.
            unsigned long long acc[4][2];
            #pragma unroll
            for (int rr = 0; rr < 4; ++rr) { acc[rr][0] = 0ull; acc[rr][1] = 0ull; }
            #pragma unroll
            for (int k = 0; k < 4; ++k) {
                uint2 w0 = *(const uint2*)&s_u[buf][0][4 * lane + 128 * k];
                uint2 w1 = *(const uint2*)&s_u[buf][1][4 * lane + 128 * k];
                const unsigned long long q0x = bf2f2(w0.x), q0y = bf2f2(w0.y);
                const unsigned long long q1x = bf2f2(w1.x), q1y = bf2f2(w1.y);
                #pragma unroll
                for (int rr = 0; rr < 4; ++rr) {
                    acc[rr][0] = fma2(e2[rr * 8 + 2 * k],     q0x, acc[rr][0]);
                    acc[rr][0] = fma2(e2[rr * 8 + 2 * k + 1], q0y, acc[rr][0]);
                    acc[rr][1] = fma2(e2[rr * 8 + 2 * k],     q1x, acc[rr][1]);
                    acc[rr][1] = fma2(e2[rr * 8 + 2 * k + 1], q1y, acc[rr][1]);
                }
            }

            // Merge-tree: lane (idx<<2) ends with total for f[idx] (idx=rr*2+bb)
            float f[8];
            #pragma unroll
            for (int rr = 0; rr < 4; ++rr) {
                f[rr * 2]     = pairsum(acc[rr][0]);
                f[rr * 2 + 1] = pairsum(acc[rr][1]);
            }
            float g0 = mrg(f[0], f[4], 16, lane);
            float g1 = mrg(f[1], f[5], 16, lane);
            float g2 = mrg(f[2], f[6], 16, lane);
            float g3 = mrg(f[3], f[7], 16, lane);
            float h0 = mrg(g0, g2, 8, lane);
            float h1 = mrg(g1, g3, 8, lane);
            float s  = mrg(h0, h1, 4, lane);
            s += __shfl_xor_sync(~0u, s, 2);
            s += __shfl_xor_sync(~0u, s, 1);

            // v' = el*s on value lanes; pair rows (rr, rr+1) with one shfl,
            // push one bf16x2 word per rank from lanes {0,4,16,20}.
            const float v  = el * s;
            const float vh = __shfl_down_sync(~0u, v, 8);   // idx+2: row rr+1, same bb
            if (isp) {
                unsigned w;
                asm("cvt.rn.bf16x2.f32 %0, %1, %2;" : "=r"(w) : "f"(vh), "f"(v));
                const int nbuf = buf ^ 1;
                const unsigned off = ((unsigned)(nbuf * 2 + pbb) * V_ + (unsigned)prow) * 2u;
                const unsigned mboff = mdelta + (unsigned)nbuf * 8u;
                #pragma unroll
                for (int rk = 0; rk < CSZ; ++rk)
                    st_async32u(pb[rk] + off, w, pb[rk] + mboff);
            }
        }
        csync();   // no CTA exits while peers may still write its SMEM
    } else {
        // =============================== FAC ===============================
        if (wid >= 4) return;
        const int b = ((int)blockIdx.x - NFCC * CSZ) * 4 + wid;   // 0..31
        const int il = ilen[b], tl = tlen[b];

        int tg[4];
        #pragma unroll
        for (int k = 0; k < 4; ++k) tg[k] = tgt[b * L_ + lane * 4 + k];

        float ts[4], tp[4];
        #pragma unroll
        for (int k = 0; k < 4; ++k) ts[k] = tr[tg[k] * V_ + tg[k]];
        const int tprev = __shfl_up_sync(~0u, tg[3], 1);
        tp[0] = tr[tg[0] * V_ + tprev];           // garbage on lane 0, never used
        tp[1] = tr[tg[1] * V_ + tg[0]];
        tp[2] = tr[tg[2] * V_ + tg[1]];
        tp[3] = tr[tg[3] * V_ + tg[2]];

        float beta[4];
        #pragma unroll
        for (int k = 0; k < 4; ++k)
            beta[k] = (lane == 0 && k == 0) ? lp[(size_t)b * V_ + tg[0]] : NEG;

        float emn[4];
        #pragma unroll
        for (int k = 0; k < 4; ++k)
            emn[k] = lp[((size_t)1 * B_ + b) * V_ + tg[k]];

        for (int t = 0; t < T_; ++t) {
            if (t == il - 1) {
                const int lsel = tl - 1;
                if (lane == (lsel >> 2)) publish(b, beta[lsel & 3], false, out);
            }
            if (t == T_ - 1) break;

            float em[4];
            #pragma unroll
            for (int k = 0; k < 4; ++k) em[k] = emn[k];
            if (t + 2 < T_) {
                #pragma unroll
                for (int k = 0; k < 4; ++k)
                    emn[k] = lp[((size_t)(t + 2) * B_ + b) * V_ + tg[k]];
            }

            const float bprev = __shfl_up_sync(~0u, beta[3], 1);
            float prevs[4] = {bprev, beta[0], beta[1], beta[2]};
            #pragma unroll
            for (int k = 0; k < 4; ++k) {
                float stay = beta[k] + ts[k];
                float move = (lane == 0 && k == 0) ? NEG : prevs[k] + tp[k];
                float hi = fmaxf(stay, move);
                float lo = fminf(stay, move);
                beta[k] = em[k] + hi + __logf(1.f + __expf(lo - hi));
            }
        }
    }
}

extern "C" void kernel_launch(void* const* d_in, const int* in_sizes, int n_in,
                              void* d_out, int out_size) {
    const float* lp  = (const float*)d_in[0];
    const float* tr  = (const float*)d_in[1];
    const int*   tgt = (const int*)d_in[2];
    const int*   il  = (const int*)d_in[3];
    const int*   tl  = (const int*)d_in[4];
    (void)in_sizes; (void)n_in; (void)out_size;

    asg_main<<<NFCC * CSZ + CSZ, NTHR>>>(lp, tr, tgt, il, tl, (float*)d_out);
}

// round 12
// speedup vs baseline: 1.5492x; 1.0880x over previous
#include <cuda_runtime.h>
#include <cstdint>

// ASG loss = FCC (log-partition over all paths) - FAC (forced alignment).
// T=512, B=32, V=512, L=128 (fixed by dataset).
//
// FCC: unnormalized probability recursion v' = exp(lp) * (E v), E in regs.
// Cluster of 8 CTAs per 2 batches. Per-step exchange uses SELF-SIGNALING
// st.async stores carrying mbarrier complete_tx credits (protocol of the
// 825us best). THIS ROUND'S ONLY CHANGE: one poller per warp (lane 0)
// waits on the tx-barrier and releases its warp via __syncwarp(), instead
// of all 512 threads polling -- kills the poll-storm contending with the
// incoming credit stream on the SMEM/mbarrier unit.
// FAC: separate CTAs, 1 warp/batch, register-resident.

namespace {
constexpr int T_ = 512, B_ = 32, V_ = 512, L_ = 128;
constexpr int CSZ = 8;      // cluster size
constexpr int ISL = 64;     // i-rows per CTA
constexpr int NTHR = 512;
constexpr int NFCC = 16;    // FCC clusters (2 batches each)
constexpr float NEG = -1000000000.0f;
constexpr unsigned FILL_BYTES = 2u * V_ * 4u;   // 4096 B per fill
}

__device__ float g_fcc[B_];
__device__ float g_fac[B_];
__device__ unsigned g_done[B_];   // parity counter, never reset

static __device__ __forceinline__ unsigned cta_rank() {
    unsigned r; asm("mov.u32 %0, %%cluster_ctarank;" : "=r"(r)); return r;
}
static __device__ __forceinline__ unsigned su32(const void* p) {
    unsigned a;
    asm("{ .reg .u64 t; cvta.to.shared.u64 t, %1; cvt.u32.u64 %0, t; }"
        : "=r"(a) : "l"(p));
    return a;
}
static __device__ __forceinline__ unsigned mapa_r(unsigned a, unsigned r) {
    unsigned o;
    asm("mapa.shared::cluster.u32 %0, %1, %2;" : "=r"(o) : "r"(a), "r"(r));
    return o;
}
static __device__ __forceinline__ void csync() {
    asm volatile("barrier.cluster.arrive.aligned;" ::: "memory");
    asm volatile("barrier.cluster.wait.aligned;" ::: "memory");
}
static __device__ __forceinline__ void mbar_init(unsigned a, unsigned cnt) {
    asm volatile("mbarrier.init.shared.b64 [%0], %1;" :: "r"(a), "r"(cnt) : "memory");
}
static __device__ __forceinline__ void mbar_expect(unsigned a, unsigned tx) {
    asm volatile("mbarrier.arrive.expect_tx.shared.b64 _, [%0], %1;"
                 :: "r"(a), "r"(tx) : "memory");
}
// Self-signaling remote store: data lands in peer SMEM, credits 4 bytes on
// the peer's mbarrier when complete.
static __device__ __forceinline__ void st_async32(unsigned a, float v, unsigned mb) {
    asm volatile("st.async.shared::cluster.mbarrier::complete_tx::bytes.b32 [%0], %1, [%2];"
                 :: "r"(a), "r"(__float_as_uint(v)), "r"(mb) : "memory");
}
static __device__ __forceinline__ void mbar_wait(unsigned a, unsigned parity) {
    unsigned done;
    asm volatile(
        "{\n\t.reg .pred p;\n\t"
        "mbarrier.try_wait.parity.acquire.cluster.shared::cta.b64 p, [%1], %2;\n\t"
        "selp.b32 %0, 1, 0, p;\n\t}"
        : "=r"(done) : "r"(a), "r"(parity) : "memory");
    if (!done) {
        asm volatile(
            "{\n\t.reg .pred P1;\n\t"
            "WL_%=:\n\t"
            "mbarrier.try_wait.parity.acquire.cluster.shared::cta.b64 P1, [%0], %1, 0x989680;\n\t"
            "@P1 bra.uni WD_%=;\n\t"
            "bra.uni WL_%=;\n\t"
            "WD_%=:\n\t}"
            :: "r"(a), "r"(parity) : "memory");
    }
}
// One poller per warp; the rest of the warp parks on __syncwarp. Lane 0's
// acquire + warp sync gives the other lanes happens-before for their
// subsequent SMEM reads.
static __device__ __forceinline__ void mbar_wait_warp(unsigned a, unsigned parity,
                                                      int lane) {
    if (lane == 0) mbar_wait(a, parity);
    __syncwarp();
}
static __device__ __forceinline__ unsigned long long fma2(
    unsigned long long a, unsigned long long b, unsigned long long c) {
    unsigned long long d;
    asm("fma.rn.f32x2 %0, %1, %2, %3;" : "=l"(d) : "l"(a), "l"(b), "l"(c));
    return d;
}
static __device__ __forceinline__ unsigned long long packf2(float lo, float hi) {
    unsigned long long d;
    asm("mov.b64 %0, {%1,%2};" : "=l"(d) : "f"(lo), "f"(hi));
    return d;
}
static __device__ __forceinline__ float pairsum(unsigned long long a) {
    float lo, hi;
    asm("mov.b64 {%0,%1}, %2;" : "=f"(lo), "=f"(hi) : "l"(a));
    return lo + hi;
}
// Merge-reduce step: combine two per-lane partial values; lanes with
// (lane & m) carry the 'b' index forward.
static __device__ __forceinline__ float mrg(float a, float b, int m, int lane) {
    float send = (lane & m) ? a : b;
    float keep = (lane & m) ? b : a;
    return keep + __shfl_xor_sync(~0u, send, m);
}

// Second arriver (parity odd) of {fcc, fac} writes the output.
static __device__ __forceinline__ void publish(int b, float val, bool is_fcc,
                                               float* __restrict__ out) {
    if (is_fcc) g_fcc[b] = val; else g_fac[b] = val;
    __threadfence();
    unsigned old = atomicAdd(&g_done[b], 1u);
    if (old & 1u) {
        __threadfence();
        out[b] = g_fcc[b] - g_fac[b];
    }
}

__global__ void __launch_bounds__(NTHR, 1) __cluster_dims__(CSZ, 1, 1)
asg_main(const float* __restrict__ lp, const float* __restrict__ tr,
         const int* __restrict__ tgt, const int* __restrict__ ilen,
         const int* __restrict__ tlen, float* __restrict__ out)
{
    __shared__ __align__(16) float s_u[2][2][V_];        // double-buffered v
    __shared__ __align__(8) unsigned long long s_mbar[2];

    const int tid  = threadIdx.x;
    const int lane = tid & 31;
    const int wid  = tid >> 5;
    const int cid  = (int)blockIdx.x >> 3;

    if (cid < NFCC) {
        // =============================== FCC ===============================
        const unsigned r = cta_rank();
        const int b0 = 2 * cid, b1 = 2 * cid + 1;
        const int len0 = ilen[b0], len1 = ilen[b1];

        // Value/push lanes: lanes 0,4,...,28 hold the 8 final sums
        // (idx = lane>>2 = rr*2 + bb).
        const bool isp = (lane & 3) == 0;
        const int idx = lane >> 2;               // 0..7 meaningful on isp lanes
        const int prr = idx >> 1, pbb = idx & 1;
        const int prow = (int)r * ISL + wid * 4 + prr;   // global row this lane pushes

        const unsigned ubase  = su32(&s_u[0][0][0]);
        const unsigned mloc0  = su32(&s_mbar[0]);
        const unsigned mdelta = mloc0 - ubase;
        unsigned pb[CSZ];
        #pragma unroll
        for (int rk = 0; rk < CSZ; ++rk) pb[rk] = mapa_r(ubase, (unsigned)rk);

        if (tid == 0) {
            mbar_init(mloc0, 1);
            mbar_init(mloc0 + 8, 1);
            mbar_expect(mloc0 + 8, FILL_BYTES);   // fill@t=0 targets mbar[1]
        }

        // E registers: warp w owns rows r*64 + 4w + rr (rr<4); lane owns
        // j in {4*lane + 128k + m}: conflict-free interleaved map.
        unsigned long long e2[32];
        #pragma unroll
        for (int rr = 0; rr < 4; ++rr) {
            const int row = (int)r * ISL + wid * 4 + rr;
            #pragma unroll
            for (int k = 0; k < 4; ++k) {
                float4 v4 = *(const float4*)(tr + (size_t)row * V_ + 4 * lane + 128 * k);
                e2[rr * 8 + 2 * k]     = packf2(__expf(v4.x), __expf(v4.y));
                e2[rr * 8 + 2 * k + 1] = packf2(__expf(v4.z), __expf(v4.w));
            }
        }

        // v_0 = exp(lp[0,b,:]); every CTA initializes buffer 0 locally.
        s_u[0][0][tid] = __expf(lp[(size_t)b0 * V_ + tid]);
        s_u[0][1][tid] = __expf(lp[(size_t)b1 * V_ + tid]);
        __syncthreads();
        csync();   // peers' mbar init + expect + buffers visible

        for (int t = 0; t < T_; ++t) {
            const int buf = t & 1;

            // Prefetch exp(lp[t+1]) for this lane's (row,batch), before wait
            float el = 0.f;
            if (isp && t + 1 < T_)
                el = __expf(lp[((size_t)(t + 1) * B_ + (pbb ? b1 : b0)) * V_ + prow]);

            // ONE poller per warp (lane 0); warp parks on __syncwarp.
            if (t) mbar_wait_warp(mloc0 + (unsigned)buf * 8,
                                  (unsigned)(((t - 1) >> 1) & 1), lane);

            // Arm this mbar for its next fill (fill@t+1), after its consume
            if (tid == 0 && t + 3 <= T_)
                mbar_expect(mloc0 + (unsigned)buf * 8, FILL_BYTES);

            // Score capture (once per batch): lse(alpha_t) = log sum_j v_j
            if (r == 0 && (wid == 8 || wid == 9)) {
                const int bs = wid - 8;
                if (t == (bs ? len1 : len0) - 1) {
                    float s = 0.f;
                    #pragma unroll
                    for (int k = 0; k < 16; ++k) s += s_u[buf][bs][lane + 32 * k];
                    #pragma unroll
                    for (int mk = 16; mk; mk >>= 1) s += __shfl_xor_sync(~0u, s, mk);
                    if (lane == 0) publish(bs ? b1 : b0, logf(s), true, out);
                }
            }
            if (t == T_ - 1) break;

            // Phase A: complete dots for 4 rows x 2 batches, lanes split j
            unsigned long long acc[4][2];
            #pragma unroll
            for (int rr = 0; rr < 4; ++rr) { acc[rr][0] = 0ull; acc[rr][1] = 0ull; }
            #pragma unroll
            for (int k = 0; k < 4; ++k) {
                ulonglong2 q0 = *(const ulonglong2*)&s_u[buf][0][4 * lane + 128 * k];
                ulonglong2 q1 = *(const ulonglong2*)&s_u[buf][1][4 * lane + 128 * k];
                #pragma unroll
                for (int rr = 0; rr < 4; ++rr) {
                    acc[rr][0] = fma2(e2[rr * 8 + 2 * k],     q0.x, acc[rr][0]);
                    acc[rr][0] = fma2(e2[rr * 8 + 2 * k + 1], q0.y, acc[rr][0]);
                    acc[rr][1] = fma2(e2[rr * 8 + 2 * k],     q1.x, acc[rr][1]);
                    acc[rr][1] = fma2(e2[rr * 8 + 2 * k + 1], q1.y, acc[rr][1]);
                }
            }

            // Merge-tree: lane (idx<<2) ends with total for f[idx] (idx=rr*2+bb)
            float f[8];
            #pragma unroll
            for (int rr = 0; rr < 4; ++rr) {
                f[rr * 2]     = pairsum(acc[rr][0]);
                f[rr * 2 + 1] = pairsum(acc[rr][1]);
            }
            float g0 = mrg(f[0], f[4], 16, lane);
            float g1 = mrg(f[1], f[5], 16, lane);
            float g2 = mrg(f[2], f[6], 16, lane);
            float g3 = mrg(f[3], f[7], 16, lane);
            float h0 = mrg(g0, g2, 8, lane);
            float h1 = mrg(g1, g3, 8, lane);
            float s  = mrg(h0, h1, 4, lane);
            s += __shfl_xor_sync(~0u, s, 2);
            s += __shfl_xor_sync(~0u, s, 1);

            // Push v' = el * s to all 8 ranks; each store self-signals the
            // destination's tx-barrier.
            if (isp) {
                const float v = el * s;
                const int nbuf = buf ^ 1;
                const unsigned off = ((unsigned)(nbuf * 2 + pbb) * V_ + (unsigned)prow) * 4u;
                const unsigned mboff = mdelta + (unsigned)nbuf * 8u;
                #pragma unroll
                for (int rk = 0; rk < CSZ; ++rk)
                    st_async32(pb[rk] + off, v, pb[rk] + mboff);
            }
        }
        csync();   // no CTA exits while peers may still write its SMEM
    } else {
        // =============================== FAC ===============================
        if (wid >= 4) return;
        const int b = ((int)blockIdx.x - NFCC * CSZ) * 4 + wid;   // 0..31
        const int il = ilen[b], tl = tlen[b];

        int tg[4];
        #pragma unroll
        for (int k = 0; k < 4; ++k) tg[k] = tgt[b * L_ + lane * 4 + k];

        float ts[4], tp[4];
        #pragma unroll
        for (int k = 0; k < 4; ++k) ts[k] = tr[tg[k] * V_ + tg[k]];
        const int tprev = __shfl_up_sync(~0u, tg[3], 1);
        tp[0] = tr[tg[0] * V_ + tprev];           // garbage on lane 0, never used
        tp[1] = tr[tg[1] * V_ + tg[0]];
        tp[2] = tr[tg[2] * V_ + tg[1]];
        tp[3] = tr[tg[3] * V_ + tg[2]];

        float beta[4];
        #pragma unroll
        for (int k = 0; k < 4; ++k)
            beta[k] = (lane == 0 && k == 0) ? lp[(size_t)b * V_ + tg[0]] : NEG;

        float emn[4];
        #pragma unroll
        for (int k = 0; k < 4; ++k)
            emn[k] = lp[((size_t)1 * B_ + b) * V_ + tg[k]];

        for (int t = 0; t < T_; ++t) {
            if (t == il - 1) {
                const int lsel = tl - 1;
                if (lane == (lsel >> 2)) publish(b, beta[lsel & 3], false, out);
            }
            if (t == T_ - 1) break;

            float em[4];
            #pragma unroll
            for (int k = 0; k < 4; ++k) em[k] = emn[k];
            if (t + 2 < T_) {
                #pragma unroll
                for (int k = 0; k < 4; ++k)
                    emn[k] = lp[((size_t)(t + 2) * B_ + b) * V_ + tg[k]];
            }

            const float bprev = __shfl_up_sync(~0u, beta[3], 1);
            float prevs[4] = {bprev, beta[0], beta[1], beta[2]};
            #pragma unroll
            for (int k = 0; k < 4; ++k) {
                float stay = beta[k] + ts[k];
                float move = (lane == 0 && k == 0) ? NEG : prevs[k] + tp[k];
                float hi = fmaxf(stay, move);
                float lo = fminf(stay, move);
                beta[k] = em[k] + hi + __logf(1.f + __expf(lo - hi));
            }
        }
    }
}

extern "C" void kernel_launch(void* const* d_in, const int* in_sizes, int n_in,
                              void* d_out, int out_size) {
    const float* lp  = (const float*)d_in[0];
    const float* tr  = (const float*)d_in[1];
    const int*   tgt = (const int*)d_in[2];
    const int*   il  = (const int*)d_in[3];
    const int*   tl  = (const int*)d_in[4];
    (void)in_sizes; (void)n_in; (void)out_size;

    asg_main<<<NFCC * CSZ + CSZ, NTHR>>>(lp, tr, tgt, il, tl, (float*)d_out);
}